// round 4
// baseline (speedup 1.0000x reference)
#include <cuda_runtime.h>
#include <math.h>

#define PI_F 3.14159265358979323846f

#define Bb   2
#define Cc   128
#define Hh   128
#define Ww   256
#define HW   32768          // Hh*Ww
#define AUXC 133
#define KWF  129            // rfft width bins

typedef unsigned long long ull;

// ---------------- packed fp32x2 helpers ----------------------------------
__device__ __forceinline__ ull pk2(float lo, float hi) {
    ull r;
    asm("mov.b64 %0, {%1,%2};" : "=l"(r) : "f"(lo), "f"(hi));
    return r;
}
__device__ __forceinline__ void fma2(ull& d, ull a, ull b) {
    asm("fma.rn.f32x2 %0, %1, %2, %0;" : "+l"(d) : "l"(a), "l"(b));
}
__device__ __forceinline__ float2 up2(ull v) {
    float2 f;
    asm("mov.b64 {%0,%1}, %2;" : "=f"(f.x), "=f"(f.y) : "l"(v));
    return f;
}

// ---------------- static scratch (no allocations allowed) ----------------
__device__ float2 g_R[Bb*KWF*Cc*Hh];      // row-FFT result, layout [b][kw][c][m]
__device__ float  g_part[Bb*KWF*64*128];  // per-channel-pair |FFT| partials
__device__ float  g_feh[Bb*Hh*KWF];       // |FFT| channel-mean, [b][kh][kw]
__device__ float  g_fe[Bb*HW];            // resized freq energy [b][h][w]
__device__ float  g_aux[Bb*AUXC*HW];      // concat(x, coord4, fe)
__device__ float  g_off[Bb*18*HW];        // offset conv output
__device__ float  g_gbuf[Bb*66*HW];       // gate hidden
__device__ float  g_gate[Bb*HW];          // sigmoid gate
__device__ float  g_ybase[Bb*Cc*HW];      // base conv output
__device__ float  g_xT[Bb*HW*Cc];         // x in NHWC for vector gathers
__device__ float  g_wP[9*Cc*Cc];          // def_w permuted to [kk*128+ci][co]

// ---------------- FFT over W (256-pt, real input, keep bins 0..128) ------
__global__ void fft_rows_k(const float* __restrict__ x) {
    __shared__ float2 sm[256];
    __shared__ float2 tw[128];
    int bid = blockIdx.x;
    int m = bid & (Hh-1);
    int c = (bid >> 7) & (Cc-1);
    int b = bid >> 14;
    int tid = threadIdx.x;
    float ang = -2.0f * PI_F * (float)tid / 256.0f;
    tw[tid] = make_float2(cosf(ang), sinf(ang));
    const float* row = x + ((size_t)(b*Cc + c)*Hh + m)*Ww;
    for (int i = tid; i < 256; i += 128) {
        int r = __brev(i) >> 24;
        sm[r] = make_float2(row[i], 0.0f);
    }
    __syncthreads();
#pragma unroll
    for (int s = 1; s <= 8; s++) {
        int half = 1 << (s-1);
        int pos = tid & (half-1);
        int i0 = ((tid >> (s-1)) << s) | pos;
        int i1 = i0 + half;
        float2 w = tw[pos << (8-s)];
        float2 a = sm[i0], bv = sm[i1];
        float2 t = make_float2(bv.x*w.x - bv.y*w.y, bv.x*w.y + bv.y*w.x);
        sm[i0] = make_float2(a.x + t.x, a.y + t.y);
        sm[i1] = make_float2(a.x - t.x, a.y - t.y);
        __syncthreads();
    }
    g_R[((size_t)(b*KWF + tid)*Cc + c)*Hh + m] = sm[tid];
    if (tid == 0)
        g_R[((size_t)(b*KWF + 128)*Cc + c)*Hh + m] = sm[128];
}

// ---------------- FFT over H: one block per (b,kw,channel-pair) ----------
__global__ void fft_cols_k(void) {
    __shared__ float2 sm[2][128];
    __shared__ float2 tw[64];
    __shared__ float  mg[128];
    int bid = blockIdx.x;
    int cp = bid & 63;
    int kw = (bid >> 6) % KWF;
    int b  = bid / (64*KWF);
    int tid = threadIdx.x;
    int lane = tid & 63;
    int f = tid >> 6;
    int c = cp*2 + f;
    if (tid < 64) {
        float ang = -2.0f * PI_F * (float)tid / 128.0f;
        tw[tid] = make_float2(cosf(ang), sinf(ang));
    }
    const float2* base = g_R + (size_t)(b*KWF + kw)*Cc*Hh + c*Hh;
#pragma unroll
    for (int i = lane; i < 128; i += 64) {
        sm[f][__brev(i) >> 25] = base[i];
    }
    __syncthreads();
#pragma unroll
    for (int s = 1; s <= 7; s++) {
        int half = 1 << (s-1);
        int pos = lane & (half-1);
        int i0 = ((lane >> (s-1)) << s) | pos;
        int i1 = i0 + half;
        float2 w = tw[pos << (7-s)];
        float2 a = sm[f][i0], bv = sm[f][i1];
        float2 t = make_float2(bv.x*w.x - bv.y*w.y, bv.x*w.y + bv.y*w.x);
        sm[f][i0] = make_float2(a.x + t.x, a.y + t.y);
        sm[f][i1] = make_float2(a.x - t.x, a.y - t.y);
        __syncthreads();
    }
    if (f == 0) {
#pragma unroll
        for (int i = lane; i < 128; i += 64) {
            float2 X = sm[0][i];
            mg[i] = sqrtf(X.x*X.x + X.y*X.y);
        }
    }
    __syncthreads();
    if (f == 1) {
#pragma unroll
        for (int i = lane; i < 128; i += 64) {
            float2 X = sm[1][i];
            g_part[(size_t)bid*128 + i] = mg[i] + sqrtf(X.x*X.x + X.y*X.y);
        }
    }
}

// ---------------- reduce 64 channel-pair partials -> g_feh ---------------
__global__ void reduce_feh_k(void) {
    int bid = blockIdx.x;           // b*KWF + kw
    int kw = bid % KWF;
    int b  = bid / KWF;
    int kh = threadIdx.x;
    float s = 0.0f;
    const float* p = g_part + (size_t)bid*64*128 + kh;
#pragma unroll 8
    for (int cp = 0; cp < 64; cp++)
        s += p[cp*128];
    float scale = 1.0f / (128.0f * sqrtf((float)(Hh*Ww)));
    g_feh[(size_t)(b*Hh + kh)*KWF + kw] = s * scale;
}

// ---------------- bilinear width resize 129 -> 256 (half-pixel, clamp) ---
__global__ void resize_fe_k(void) {
    int idx = blockIdx.x*blockDim.x + threadIdx.x;
    if (idx >= Bb*HW) return;
    int w = idx & (Ww-1);
    int h = (idx >> 8) & (Hh-1);
    int b = idx >> 15;
    float px = ((float)w + 0.5f) * (129.0f/256.0f) - 0.5f;
    float x0f = floorf(px);
    float f = px - x0f;
    int x0 = (int)x0f;
    int x1 = x0 + 1;
    x0 = min(max(x0, 0), 128);
    x1 = min(max(x1, 0), 128);
    const float* r = g_feh + (size_t)(b*Hh + h)*KWF;
    g_fe[idx] = r[x0]*(1.0f-f) + r[x1]*f;
}

// ---------------- aux = concat(x, sin/cos coords, fe) --------------------
__global__ void build_aux_k(const float* __restrict__ x) {
    int idx = blockIdx.x*blockDim.x + threadIdx.x;
    if (idx >= Bb*AUXC*HW) return;
    int w  = idx & (Ww-1);
    int h  = (idx >> 8) & (Hh-1);
    int ci = (idx / HW) % AUXC;
    int b  = idx / (AUXC*HW);
    float v;
    if (ci < Cc) {
        v = x[((size_t)(b*Cc + ci)*Hh + h)*Ww + w];
    } else if (ci == Cc) {
        float th = -PI_F + (2.0f*PI_F/255.0f)*(float)w; v = sinf(th);
    } else if (ci == Cc+1) {
        float th = -PI_F + (2.0f*PI_F/255.0f)*(float)w; v = cosf(th);
    } else if (ci == Cc+2) {
        float ph = -0.5f*PI_F + (PI_F/127.0f)*(float)h; v = sinf(ph);
    } else if (ci == Cc+3) {
        float ph = -0.5f*PI_F + (PI_F/127.0f)*(float)h; v = cosf(ph);
    } else {
        v = g_fe[(size_t)b*HW + h*Ww + w];
    }
    g_aux[idx] = v;
}

// ---------------- NCHW -> NHWC transpose of x ----------------------------
__global__ void transpose_k(const float* __restrict__ x) {
    __shared__ float t[32][33];
    int b  = blockIdx.z;
    int p0 = blockIdx.x * 32;   // hw
    int c0 = blockIdx.y * 32;   // channel
    int tx = threadIdx.x, ty = threadIdx.y;
#pragma unroll
    for (int j = 0; j < 4; j++)
        t[ty + j*8][tx] = x[(size_t)(b*Cc + c0 + ty + j*8)*HW + p0 + tx];
    __syncthreads();
#pragma unroll
    for (int j = 0; j < 4; j++)
        g_xT[(size_t)(b*HW + p0 + ty + j*8)*Cc + c0 + tx] = t[tx][ty + j*8];
}

// ---------------- def_w (co,ci,kk) -> wP[kk*128+ci][co] ------------------
__global__ void permw_k(const float* __restrict__ dw) {
    int idx = blockIdx.x*blockDim.x + threadIdx.x;
    if (idx >= 9*Cc*Cc) return;
    int co = idx & 127;
    int ci = (idx >> 7) & 127;
    int kk = idx >> 14;
    g_wP[idx] = dw[(size_t)(co*Cc + ci)*9 + kk];
}

// ---------------- direct 3x3 conv, pad 1, NCHW, f32x2 --------------------
// block: 32 couts x (32w x 8h) pixels; thread: 4 couts x 8 rows (4 y-pairs)
// IN_SEL: 0 = g_aux, 1 = external pointer (x)
// OUT_SEL: 0 = g_off, 1 = g_gbuf, 2 = g_ybase
template<int IN_SEL, int OUT_SEL, int CIN, int COUT, int RELU>
__global__ void __launch_bounds__(256) conv3x3_t(
        const float* __restrict__ xin, const float* __restrict__ wgt,
        const float* __restrict__ bias) {
    const float* in = (IN_SEL == 0) ? g_aux : xin;
    float* out = (OUT_SEL == 0) ? g_off : (OUT_SEL == 1) ? g_gbuf : g_ybase;
    __shared__ float tile[10][34];
    __shared__ ull   ws2[32][9];
    int tid = threadIdx.x;
    int xt = tid & 31;
    int ct = tid >> 5;                  // 0..7
    int x0 = blockIdx.x * 32;
    int y0 = blockIdx.y * 8;
    const int nCoBlk = (COUT + 31) >> 5;
    int b   = blockIdx.z / nCoBlk;
    int coB = (blockIdx.z % nCoBlk) * 32;
    ull acc[4][4];
#pragma unroll
    for (int j = 0; j < 4; j++)
#pragma unroll
        for (int yp = 0; yp < 4; yp++) acc[j][yp] = 0ULL;

    for (int ci = 0; ci < CIN; ci++) {
        const float* ip = in + (size_t)(b*CIN + ci)*HW;
#pragma unroll
        for (int i = tid; i < 340; i += 256) {
            int r = i / 34, cc = i % 34;
            int gy = y0 + r - 1, gx = x0 + cc - 1;
            float v = 0.0f;
            if (gy >= 0 && gy < Hh && gx >= 0 && gx < Ww) v = ip[gy*Ww + gx];
            tile[r][cc] = v;
        }
#pragma unroll
        for (int i = tid; i < 288; i += 256) {
            int co = i / 9, tap = i % 9;
            int gco = coB + co;
            float w = (gco < COUT) ? wgt[(size_t)(gco*CIN + ci)*9 + tap] : 0.0f;
            ws2[co][tap] = pk2(w, w);
        }
        __syncthreads();
        // packed row pairs vp[r] = (tile[r], tile[r+1]) at cols xt..xt+2
        ull vp[9][3];
        {
            float pr0 = tile[0][xt], pr1 = tile[0][xt+1], pr2 = tile[0][xt+2];
#pragma unroll
            for (int r = 1; r < 10; r++) {
                float c0v = tile[r][xt], c1v = tile[r][xt+1], c2v = tile[r][xt+2];
                vp[r-1][0] = pk2(pr0, c0v);
                vp[r-1][1] = pk2(pr1, c1v);
                vp[r-1][2] = pk2(pr2, c2v);
                pr0 = c0v; pr1 = c1v; pr2 = c2v;
            }
        }
#pragma unroll
        for (int j = 0; j < 4; j++) {
            int co = ct*4 + j;
            ull wr2[9];
#pragma unroll
            for (int t = 0; t < 9; t++) wr2[t] = ws2[co][t];
#pragma unroll
            for (int yp = 0; yp < 4; yp++) {
                ull s = acc[j][yp];
#pragma unroll
                for (int t = 0; t < 9; t++) {
                    int r = t / 3, k = t % 3;
                    fma2(s, vp[yp*2 + r][k], wr2[t]);
                }
                acc[j][yp] = s;
            }
        }
        __syncthreads();
    }
#pragma unroll
    for (int j = 0; j < 4; j++) {
        int co = coB + ct*4 + j;
        if (co < COUT) {
            float bs = bias[co];
            float* op = out + (size_t)(b*COUT + co)*HW + (size_t)y0*Ww + x0 + xt;
#pragma unroll
            for (int yp = 0; yp < 4; yp++) {
                float2 o = up2(acc[j][yp]);
                o.x += bs; o.y += bs;
                if (RELU) { o.x = fmaxf(o.x, 0.0f); o.y = fmaxf(o.y, 0.0f); }
                op[(yp*2    )*Ww] = o.x;
                op[(yp*2 + 1)*Ww] = o.y;
            }
        }
    }
}

// ---------------- 1x1 gate conv + sigmoid --------------------------------
__global__ void gate1x1_k(const float* __restrict__ w2, const float* __restrict__ b2) {
    int idx = blockIdx.x*blockDim.x + threadIdx.x;
    if (idx >= Bb*HW) return;
    int b = idx >> 15;
    int p = idx & (HW-1);
    float s = b2[0];
#pragma unroll 6
    for (int c = 0; c < 66; c++)
        s = fmaf(g_gbuf[(size_t)(b*66 + c)*HW + p], w2[c], s);
    g_gate[idx] = 1.0f / (1.0f + expf(-s));
}

// ---------------- fused deform-sample + 1x1 (K=1152 GEMM) + blend --------
// block: 128 couts x 128 pixels; thread: 8x8 register tile, f32x2 math
__global__ void __launch_bounds__(256) deform_gemm_k(
        const float* __restrict__ defb, float* __restrict__ out) {
    __shared__ __align__(16) float Ssm[32][128];
    __shared__ __align__(16) float Wsm[32][128];
    __shared__ int   mX0[128], mY0[128];
    __shared__ float mFx[128], mFy[128];
    int tid = threadIdx.x;
    int blk = blockIdx.x;
    int b    = blk >> 8;                 // 256 pixel-blocks per batch
    int pix0 = (blk & 255) * 128;
    int coIdx = (tid & 15) * 8;
    int pxIdx = (tid >> 4) * 8;
    ull acc[8][4];
#pragma unroll
    for (int i = 0; i < 8; i++)
#pragma unroll
        for (int j = 0; j < 4; j++) acc[i][j] = 0ULL;
    int p = tid >> 1, sub = tid & 1;

#pragma unroll 1
    for (int kk = 0; kk < 9; kk++) {
        __syncthreads();
        if (tid < 128) {
            int pp = pix0 + tid;
            int hh = pp >> 8, ww = pp & (Ww-1);
            float ox = g_off[(size_t)(b*18 + 2*kk    )*HW + pp];
            float oy = g_off[(size_t)(b*18 + 2*kk + 1)*HW + pp];
            float fpx = (float)ww + ox;
            float fpy = (float)hh + oy;
            float fx0 = floorf(fpx), fy0 = floorf(fpy);
            mX0[tid] = (int)fx0;  mY0[tid] = (int)fy0;
            mFx[tid] = fpx - fx0; mFy[tid] = fpy - fy0;
        }
        __syncthreads();
        int X0 = mX0[p], Y0 = mY0[p];
        float fx = mFx[p], fy = mFy[p];
        float w00 = (1.0f-fx)*(1.0f-fy), w10 = fx*(1.0f-fy);
        float w01 = (1.0f-fx)*fy,        w11 = fx*fy;
        if (X0   < 0 || X0   >= Ww) { w00 = 0.0f; w01 = 0.0f; }
        if (X0+1 < 0 || X0+1 >= Ww) { w10 = 0.0f; w11 = 0.0f; }
        if (Y0   < 0 || Y0   >= Hh) { w00 = 0.0f; w10 = 0.0f; }
        if (Y0+1 < 0 || Y0+1 >= Hh) { w01 = 0.0f; w11 = 0.0f; }
        ull w00p = pk2(w00, w00), w10p = pk2(w10, w10);
        ull w01p = pk2(w01, w01), w11p = pk2(w11, w11);
        int cx0 = min(max(X0,   0), Ww-1), cx1 = min(max(X0+1, 0), Ww-1);
        int cy0 = min(max(Y0,   0), Hh-1), cy1 = min(max(Y0+1, 0), Hh-1);
        const ulonglong2* p00 = (const ulonglong2*)(g_xT + ((size_t)(b*Hh + cy0)*Ww + cx0)*Cc);
        const ulonglong2* p10 = (const ulonglong2*)(g_xT + ((size_t)(b*Hh + cy0)*Ww + cx1)*Cc);
        const ulonglong2* p01 = (const ulonglong2*)(g_xT + ((size_t)(b*Hh + cy1)*Ww + cx0)*Cc);
        const ulonglong2* p11 = (const ulonglong2*)(g_xT + ((size_t)(b*Hh + cy1)*Ww + cx1)*Cc);

#pragma unroll 1
        for (int cc = 0; cc < 4; cc++) {
            __syncthreads();
            int cb  = sub * 16;             // within-chunk ci
            int cig = cc*32 + cb;           // global ci
#pragma unroll
            for (int q = 0; q < 4; q++) {
                int f4 = (cig >> 2) + q;
                ulonglong2 a00 = p00[f4], a10 = p10[f4], a01 = p01[f4], a11 = p11[f4];
                ull r01 = 0ULL, r23 = 0ULL;
                fma2(r01, w00p, a00.x); fma2(r01, w10p, a10.x);
                fma2(r01, w01p, a01.x); fma2(r01, w11p, a11.x);
                fma2(r23, w00p, a00.y); fma2(r23, w10p, a10.y);
                fma2(r23, w01p, a01.y); fma2(r23, w11p, a11.y);
                float2 f01 = up2(r01), f23 = up2(r23);
                Ssm[cb + q*4 + 0][p] = f01.x;
                Ssm[cb + q*4 + 1][p] = f01.y;
                Ssm[cb + q*4 + 2][p] = f23.x;
                Ssm[cb + q*4 + 3][p] = f23.y;
            }
            int krow0 = kk*128 + cc*32;
            {
                const float4* wsrc = (const float4*)(g_wP + (size_t)krow0*Cc);
                float4* wdst = (float4*)&Wsm[0][0];
#pragma unroll
                for (int i = tid; i < 1024; i += 256)
                    wdst[i] = wsrc[i];
            }
            __syncthreads();
#pragma unroll 8
            for (int kq = 0; kq < 32; kq++) {
                float4 a0 = *(const float4*)&Wsm[kq][coIdx];
                float4 a1 = *(const float4*)&Wsm[kq][coIdx+4];
                ulonglong2 bq0 = *(const ulonglong2*)&Ssm[kq][pxIdx];
                ulonglong2 bq1 = *(const ulonglong2*)&Ssm[kq][pxIdx+4];
                ull bv[4] = {bq0.x, bq0.y, bq1.x, bq1.y};
                float av[8] = {a0.x,a0.y,a0.z,a0.w,a1.x,a1.y,a1.z,a1.w};
#pragma unroll
                for (int i = 0; i < 8; i++) {
                    ull ap = pk2(av[i], av[i]);
#pragma unroll
                    for (int j = 0; j < 4; j++)
                        fma2(acc[i][j], ap, bv[j]);
                }
            }
        }
    }
    // epilogue: out = (1-gate)*y_base + gate*(y_def + bias)
    int pixg = pix0 + pxIdx;
    float gt[8];
#pragma unroll
    for (int j = 0; j < 8; j++) gt[j] = g_gate[(size_t)b*HW + pixg + j];
#pragma unroll
    for (int i = 0; i < 8; i++) {
        int co = coIdx + i;
        float bs = defb[co];
        const float* yb = g_ybase + (size_t)(b*Cc + co)*HW + pixg;
        float* op = out + (size_t)(b*Cc + co)*HW + pixg;
#pragma unroll
        for (int j4 = 0; j4 < 4; j4++) {
            float2 yd = up2(acc[i][j4]);
            int j0 = j4*2, j1 = j4*2 + 1;
            float y0v = yd.x + bs, y1v = yd.y + bs;
            op[j0] = (1.0f - gt[j0])*yb[j0] + gt[j0]*y0v;
            op[j1] = (1.0f - gt[j1])*yb[j1] + gt[j1]*y1v;
        }
    }
}

// ---------------- host launcher ------------------------------------------
extern "C" void kernel_launch(void* const* d_in, const int* in_sizes, int n_in,
                              void* d_out, int out_size) {
    const float* x      = (const float*)d_in[0];
    const float* off_w  = (const float*)d_in[1];
    const float* off_b  = (const float*)d_in[2];
    const float* gw1    = (const float*)d_in[3];
    const float* gb1    = (const float*)d_in[4];
    const float* gw2    = (const float*)d_in[5];
    const float* gb2    = (const float*)d_in[6];
    const float* base_w = (const float*)d_in[7];
    const float* base_b = (const float*)d_in[8];
    const float* def_w  = (const float*)d_in[9];
    const float* def_b  = (const float*)d_in[10];
    float* out = (float*)d_out;

    fft_rows_k<<<Bb*Cc*Hh, 128>>>(x);
    fft_cols_k<<<Bb*KWF*64, 128>>>();
    reduce_feh_k<<<Bb*KWF, 128>>>();
    resize_fe_k<<<(Bb*HW + 255)/256, 256>>>();
    build_aux_k<<<(Bb*AUXC*HW + 255)/256, 256>>>(x);
    transpose_k<<<dim3(HW/32, Cc/32, Bb), dim3(32, 8)>>>(x);
    permw_k<<<(9*Cc*Cc + 255)/256, 256>>>(def_w);

    conv3x3_t<0, 0, AUXC, 18, 0><<<dim3(8, 16, Bb*1), 256>>>(nullptr, off_w, off_b);
    conv3x3_t<0, 1, AUXC, 66, 1><<<dim3(8, 16, Bb*3), 256>>>(nullptr, gw1, gb1);
    conv3x3_t<1, 2, Cc,  Cc,  0><<<dim3(8, 16, Bb*4), 256>>>(x, base_w, base_b);
    gate1x1_k<<<(Bb*HW + 255)/256, 256>>>(gw2, gb2);
    deform_gemm_k<<<Bb*(HW/128), 256>>>(def_b, out);
}